// round 11
// baseline (speedup 1.0000x reference)
#include <cuda_runtime.h>
#include <cstdint>

#define N 4096
#define D 128
#define HB1 256   // pass1 blocks
#define HB2 256   // pass2 blocks
#define GB  528   // gemm blocks

// ---------------- device globals (all accumulators have identity == 0) ----------------
__device__ __align__(16) float g_en[N * D];
__device__ unsigned char g_low[N];
__device__ unsigned g_rowMinInv[N];      // ~encodeF(min pos-dot), atomicMax, 0 = empty
__device__ unsigned g_rowMaxNeg[N];      // encodeF(max neg-dot), atomicMax, 0 = empty
__device__ unsigned g_hist1[4096];
__device__ unsigned g_hist2[4096];
__device__ unsigned g_hist20[1 << 20];   // exact-value hist within p1 prefix (bits 19:0)
__device__ unsigned g_zeroPairs;
__device__ unsigned g_doneCtr[4];
__device__ unsigned g_p1, g_r1, g_mLo, g_mHi;
__device__ float    g_frac;
__device__ unsigned g_minCrossInv;       // ~min b with top12 > p1, atomicMax, 0 = empty
__device__ float    g_actT;

__device__ __forceinline__ unsigned encodeF(float f) {
    unsigned u = __float_as_uint(f);
    return (u & 0x80000000u) ? ~u : (u | 0x80000000u);
}
__device__ __forceinline__ float decodeF(unsigned u) {
    return (u & 0x80000000u) ? __uint_as_float(u & 0x7FFFFFFFu)
                             : __uint_as_float(~u);
}

__device__ __forceinline__ void rankMath(unsigned z, unsigned& mLo, unsigned& mHi, float& frac) {
    unsigned long long n = 16773120ull - 2ull * (unsigned long long)z;
    float nf = (float)(n - 1ull);
    float pos = 0.2f * nf;
    float lof = floorf(pos);
    frac = pos - lof;
    unsigned fl = (unsigned)lof;
    mLo = fl >> 1;
    mHi = (fl + 1u) >> 1;
}

// ---- locate rank in a GLOBAL 4096-bin histogram; 256-thread block; __ldcg ----
__device__ void locateG4096(const unsigned* gh, unsigned rank,
                            volatile unsigned* wS,
                            volatile unsigned* outBin, volatile unsigned* outRem) {
    int tid = threadIdx.x, lane = tid & 31, wid = tid >> 5;
    unsigned hl[16];
    unsigned lsum = 0;
#pragma unroll
    for (int k = 0; k < 16; k++) { hl[k] = __ldcg(&gh[tid * 16 + k]); lsum += hl[k]; }
    unsigned v = lsum;
#pragma unroll
    for (int s = 1; s < 32; s <<= 1) {
        unsigned o = __shfl_up_sync(0xffffffffu, v, s);
        if (lane >= s) v += o;
    }
    if (lane == 31) wS[wid] = v;
    __syncthreads();
    if (tid == 0) { unsigned run = 0; for (int w = 0; w < 8; w++) { run += wS[w]; wS[w] = run; } }
    __syncthreads();
    unsigned cum = (v - lsum) + (wid ? wS[wid - 1] : 0u);
#pragma unroll
    for (int k = 0; k < 16; k++) {
        unsigned h = hl[k];
        if (h && rank >= cum && rank < cum + h) { *outBin = (unsigned)(tid * 16 + k); *outRem = rank - cum; }
        cum += h;
    }
    __syncthreads();
}

// ---- locate rank in GLOBAL 256-entry table (bin, rem, cnt); 256-thread block ----
__device__ void locateG256(const unsigned* gh, unsigned rank,
                           volatile unsigned* wS,
                           volatile unsigned* outBin, volatile unsigned* outRem,
                           volatile unsigned* outCnt) {
    int tid = threadIdx.x, lane = tid & 31, wid = tid >> 5;
    unsigned h = __ldcg(&gh[tid]);
    unsigned v = h;
#pragma unroll
    for (int s = 1; s < 32; s <<= 1) {
        unsigned o = __shfl_up_sync(0xffffffffu, v, s);
        if (lane >= s) v += o;
    }
    if (lane == 31) wS[wid] = v;
    __syncthreads();
    if (tid == 0) { unsigned run = 0; for (int w = 0; w < 8; w++) { run += wS[w]; wS[w] = run; } }
    __syncthreads();
    unsigned cum = (v - h) + (wid ? wS[wid - 1] : 0u);
    if (h && rank >= cum && rank < cum + h) { *outBin = (unsigned)tid; *outRem = rank - cum; *outCnt = h; }
    __syncthreads();
}

// ---- locate rank in SHARED 4096-bin histogram; 256-thread block ----
__device__ void locateS4096(const unsigned* h, unsigned rank,
                            volatile unsigned* wS,
                            volatile unsigned* outBin, volatile unsigned* outRem) {
    int tid = threadIdx.x, lane = tid & 31, wid = tid >> 5;
    unsigned hl[16];
    unsigned lsum = 0;
#pragma unroll
    for (int k = 0; k < 16; k++) { hl[k] = h[tid * 16 + k]; lsum += hl[k]; }
    unsigned v = lsum;
#pragma unroll
    for (int s = 1; s < 32; s <<= 1) {
        unsigned o = __shfl_up_sync(0xffffffffu, v, s);
        if (lane >= s) v += o;
    }
    if (lane == 31) wS[wid] = v;
    __syncthreads();
    if (tid == 0) { unsigned run = 0; for (int w = 0; w < 8; w++) { run += wS[w]; wS[w] = run; } }
    __syncthreads();
    unsigned cum = (v - lsum) + (wid ? wS[wid - 1] : 0u);
#pragma unroll
    for (int k = 0; k < 16; k++) {
        unsigned hh = hl[k];
        if (hh && rank >= cum && rank < cum + hh) { *outBin = (unsigned)(tid * 16 + k); *outRem = rank - cum; }
        cum += hh;
    }
    __syncthreads();
}

// ================ K1: [pass1: bids 0-255] + [normalize+zero20: 256-383] + [median: 384] ================
__global__ __launch_bounds__(256) void prepPass1K(const float* __restrict__ t,
                                                  const float* __restrict__ emb,
                                                  const float* __restrict__ au) {
    __shared__ __align__(16) unsigned char sbuf[32768];
    __shared__ unsigned wS[8];
    __shared__ unsigned sA, sB_;
    __shared__ unsigned sAgg;
    __shared__ int sLast;
    int tid = threadIdx.x;
    int bid = blockIdx.x;

    if (bid < HB1) {
        // ---------------- pass 1: 12-bit smem histogram + tie count ----------------
        float4* tsv4 = (float4*)sbuf;
        unsigned* hist = (unsigned*)(sbuf + 16384);
        const float* tss = (const float*)tsv4;
        for (int k = tid; k < 1024; k += 256) tsv4[k] = ((const float4*)t)[k];
        for (int x = tid; x < 4096; x += 256) hist[x] = 0u;
        if (tid == 0) sAgg = 0u;
        __syncthreads();

        unsigned zc = 0u;
        for (int i = bid; i < N; i += HB1) {
            float ti = tss[i];
            int v0 = (i + 1) >> 2;
            for (int v = v0 + tid; v < 1024; v += 256) {
                float4 w = tsv4[v];
                int jb = v << 2;
#pragma unroll
                for (int k = 0; k < 4; k++) {
                    float tj = (k == 0) ? w.x : (k == 1) ? w.y : (k == 2) ? w.z : w.w;
                    if (jb + k > i) {
                        unsigned b = __float_as_uint(fabsf(ti - tj));
                        if (b == 0u) zc++;
                        else atomicAdd(&hist[b >> 20], 1u);
                    }
                }
            }
        }
        __syncthreads();
        for (int x = tid; x < 4096; x += 256)
            if (hist[x]) atomicAdd(&g_hist1[x], hist[x]);
#pragma unroll
        for (int s = 16; s > 0; s >>= 1) zc += __shfl_xor_sync(0xffffffffu, zc, s);
        if ((tid & 31) == 0 && zc) atomicAdd(&sAgg, zc);
        __syncthreads();
        if (tid == 0 && sAgg) atomicAdd(&g_zeroPairs, sAgg);

        __threadfence();
        if (tid == 0) sLast = (atomicAdd(&g_doneCtr[0], 1u) == (unsigned)(HB1 - 1)) ? 1 : 0;
        __syncthreads();
        if (!sLast) return;

        unsigned z = __ldcg(&g_zeroPairs);
        unsigned mLo, mHi; float frac;
        rankMath(z, mLo, mHi, frac);
        locateG4096(g_hist1, mLo, wS, &sA, &sB_);
        if (tid == 0) {
            g_p1 = sA; g_r1 = sB_;
            g_mLo = mLo; g_mHi = mHi; g_frac = frac;
        }
        return;
    }

    if (bid < HB1 + 128) {
        // ---------------- normalize 32 rows + zero hist20 slice ----------------
        int nb = bid - HB1;
        for (int x = tid; x < 8192; x += 256) g_hist20[nb * 8192 + x] = 0u;
        int warp = tid >> 5, lane = tid & 31;
#pragma unroll
        for (int q = 0; q < 4; q++) {
            int row = nb * 32 + warp * 4 + q;
            const float4* p = (const float4*)(emb + (size_t)row * D);
            float4 v = p[lane];
            float ss = v.x * v.x + v.y * v.y + v.z * v.z + v.w * v.w;
#pragma unroll
            for (int st = 16; st > 0; st >>= 1) ss += __shfl_xor_sync(0xffffffffu, ss, st);
            float inv = 1.0f / fmaxf(sqrtf(ss), 1e-12f);
            float4 o;
            o.x = v.x * inv; o.y = v.y * inv; o.z = v.z * inv; o.w = v.w * inv;
            ((float4*)(g_en + (size_t)row * D))[lane] = o;
        }
        return;
    }

    // ---------------- median of au via 3-level radix select (ranks 2047, 2048) ----------------
    {
        unsigned* e = (unsigned*)sbuf;
        unsigned* h = (unsigned*)(sbuf + 16384);
        for (int i = tid; i < N; i += 256) e[i] = encodeF(au[i]);
        __syncthreads();
        float vals[2];
#pragma unroll 1
        for (int r = 0; r < 2; r++) {
            unsigned rank = 2047u + (unsigned)r;
            for (int x = tid; x < 4096; x += 256) h[x] = 0u;
            __syncthreads();
            for (int i = tid; i < N; i += 256) atomicAdd(&h[e[i] >> 20], 1u);
            __syncthreads();
            locateS4096(h, rank, wS, &sA, &sB_);
            unsigned b1 = sA, r1 = sB_;
            __syncthreads();
            for (int x = tid; x < 4096; x += 256) h[x] = 0u;
            __syncthreads();
            for (int i = tid; i < N; i += 256)
                if ((e[i] >> 20) == b1) atomicAdd(&h[(e[i] >> 8) & 0xFFFu], 1u);
            __syncthreads();
            locateS4096(h, r1, wS, &sA, &sB_);
            unsigned b2 = sA, r2 = sB_;
            unsigned pfx = (b1 << 12) | b2;
            __syncthreads();
            for (int x = tid; x < 4096; x += 256) h[x] = 0u;
            __syncthreads();
            for (int i = tid; i < N; i += 256)
                if ((e[i] >> 8) == pfx) atomicAdd(&h[e[i] & 0xFFu], 1u);
            __syncthreads();
            locateS4096(h, r2, wS, &sA, &sB_);
            unsigned b3 = sA;
            __syncthreads();
            vals[r] = decodeF((b1 << 20) | (b2 << 8) | b3);
        }
        float th = __fadd_rn(__fmul_rn(vals[0], 0.5f), __fmul_rn(vals[1], 0.5f));
        for (int i = tid; i < N; i += 256) g_low[i] = (au[i] < th) ? 1 : 0;
    }
}

// ================ K2: pass 2 only (hist2 + exact hist20 + cross-min; last block selects) ================
__global__ __launch_bounds__(256) void pass2K(const float* __restrict__ t) {
    __shared__ __align__(16) unsigned char sbuf[32768];
    __shared__ unsigned wS[8];
    __shared__ unsigned sA, sB_, sC_, sD_;
    __shared__ unsigned sAgg;
    __shared__ int sLast;
    int tid = threadIdx.x;

    float4* tsv4 = (float4*)sbuf;
    unsigned* sh2 = (unsigned*)(sbuf + 16384);
    const float* tss = (const float*)tsv4;
    for (int k = tid; k < 1024; k += 256) tsv4[k] = ((const float4*)t)[k];
    for (int x = tid; x < 4096; x += 256) sh2[x] = 0u;
    if (tid == 0) sAgg = 0u;
    unsigned p1 = g_p1;   // written in K1 (previous launch)
    __syncthreads();

    unsigned myInv = 0u;
    for (int i = blockIdx.x; i < N; i += HB2) {
        float ti = tss[i];
        int v0 = (i + 1) >> 2;
        for (int v = v0 + tid; v < 1024; v += 256) {
            float4 w = tsv4[v];
            int jb = v << 2;
#pragma unroll
            for (int k = 0; k < 4; k++) {
                float tj = (k == 0) ? w.x : (k == 1) ? w.y : (k == 2) ? w.z : w.w;
                if (jb + k > i) {
                    unsigned b = __float_as_uint(fabsf(ti - tj));
                    if (b != 0u) {
                        unsigned t12 = b >> 20;
                        if (t12 == p1) {
                            atomicAdd(&sh2[(b >> 8) & 0xFFFu], 1u);
                            atomicAdd(&g_hist20[b & 0xFFFFFu], 1u);
                        } else if (t12 > p1) {
                            myInv = max(myInv, ~b);
                        }
                    }
                }
            }
        }
    }
    __syncthreads();
    for (int x = tid; x < 4096; x += 256)
        if (sh2[x]) atomicAdd(&g_hist2[x], sh2[x]);
#pragma unroll
    for (int s = 16; s > 0; s >>= 1) myInv = max(myInv, __shfl_xor_sync(0xffffffffu, myInv, s));
    if ((tid & 31) == 0 && myInv) atomicMax(&sAgg, myInv);
    __syncthreads();
    if (tid == 0 && sAgg) atomicMax(&g_minCrossInv, sAgg);

    __threadfence();
    if (tid == 0) sLast = (atomicAdd(&g_doneCtr[1], 1u) == (unsigned)(HB2 - 1)) ? 1 : 0;
    __syncthreads();
    if (!sLast) return;

    // ---- selection: exact vlo, multiplicity, next distinct value ----
    unsigned r1 = g_r1;
    locateG4096(g_hist2, r1, wS, &sA, &sB_);
    unsigned bin2 = sA, rem2 = sB_;
    __syncthreads();
    locateG256(&g_hist20[bin2 << 8], rem2, wS, &sA, &sB_, &sC_);
    unsigned bin3 = sA, rem3 = sB_, cnt3 = sC_;
    __syncthreads();
    if (tid == 0) { sA = 0xFFFFFFFFu; sB_ = 0xFFFFFFFFu; sD_ = 0xFFFFFFFFu; }
    __syncthreads();
    if ((unsigned)tid > bin3 && __ldcg(&g_hist20[(bin2 << 8) + tid]) != 0u)
        atomicMin(&sA, (unsigned)tid);
#pragma unroll
    for (int k = 0; k < 16; k++) {
        unsigned idx = (unsigned)tid * 16u + (unsigned)k;
        if (idx > bin2 && __ldcg(&g_hist2[idx]) != 0u) atomicMin(&sB_, idx);
    }
    __syncthreads();
    unsigned nextA = sA, nbin2 = sB_;
    if (nbin2 != 0xFFFFFFFFu) {
        if (__ldcg(&g_hist20[(nbin2 << 8) + tid]) != 0u) atomicMin(&sD_, (unsigned)tid);
    }
    __syncthreads();
    if (tid == 0) {
        unsigned vlo = (p1 << 20) | (bin2 << 8) | bin3;
        unsigned mLo = g_mLo, mHi = g_mHi;
        float frac = g_frac;
        unsigned mAb = 0xFFFFFFFFu;
        if (nextA != 0xFFFFFFFFu) mAb = min(mAb, (p1 << 20) | (bin2 << 8) | nextA);
        if (nbin2 != 0xFFFFFFFFu && sD_ != 0xFFFFFFFFu)
            mAb = min(mAb, (p1 << 20) | (nbin2 << 8) | sD_);
        unsigned crossInv = __ldcg(&g_minCrossInv);
        if (crossInv) mAb = min(mAb, ~crossInv);
        bool same = (mHi == mLo) || (rem3 + 1u < cnt3);
        float flo = __uint_as_float(vlo);
        float fhi = same ? flo : __uint_as_float(mAb);
        g_actT = __fadd_rn(__fmul_rn(flo, 1.0f - frac), __fmul_rn(fhi, frac));
    }
}

// ================ K3: symmetric packed-f32x2 GEMM + epilogue; last block: final + resets ================
__global__ __launch_bounds__(256) void gemmK(const float* __restrict__ t,
                                             float* __restrict__ out, int out_size) {
    __shared__ __align__(16) unsigned char sbuf[43008];
    __shared__ int sLast;
    int tid = threadIdx.x;

    float (*As)[136] = (float (*)[136])sbuf;
    float (*Bs)[136] = (float (*)[136])(sbuf + 17408);
    unsigned* sColMin = (unsigned*)(sbuf + 34816);   // [8][128]
    unsigned* sColMax = (unsigned*)(sbuf + 38912);   // [8][128]

    int b = blockIdx.x;
    int bi = 0;
    while (b >= 32 - bi) { b -= 32 - bi; bi++; }
    int bj = bi + b;
    int ri = bi * 128, rj = bj * 128;

    int r0 = (tid >> 4) * 4;
    int c0 = (tid & 15) * 4;

    unsigned long long acc2[8][4];
#pragma unroll
    for (int r = 0; r < 8; r++)
#pragma unroll
        for (int c = 0; c < 4; c++) acc2[r][c] = 0ull;

    int lr = tid >> 1, lh = tid & 1;
    for (int kc = 0; kc < 4; kc++) {
        const float4* pa = (const float4*)(g_en + (size_t)(ri + lr) * D + kc * 32 + lh * 16);
        const float4* pb = (const float4*)(g_en + (size_t)(rj + lr) * D + kc * 32 + lh * 16);
        float4 a0 = pa[0], a1 = pa[1], a2 = pa[2], a3 = pa[3];
        float4 b0 = pb[0], b1 = pb[1], b2 = pb[2], b3 = pb[3];
        if (kc) __syncthreads();
        int kb = lh * 16;
        As[kb + 0][lr] = a0.x; As[kb + 1][lr] = a0.y; As[kb + 2][lr] = a0.z; As[kb + 3][lr] = a0.w;
        As[kb + 4][lr] = a1.x; As[kb + 5][lr] = a1.y; As[kb + 6][lr] = a1.z; As[kb + 7][lr] = a1.w;
        As[kb + 8][lr] = a2.x; As[kb + 9][lr] = a2.y; As[kb + 10][lr] = a2.z; As[kb + 11][lr] = a2.w;
        As[kb + 12][lr] = a3.x; As[kb + 13][lr] = a3.y; As[kb + 14][lr] = a3.z; As[kb + 15][lr] = a3.w;
        Bs[kb + 0][lr] = b0.x; Bs[kb + 1][lr] = b0.y; Bs[kb + 2][lr] = b0.z; Bs[kb + 3][lr] = b0.w;
        Bs[kb + 4][lr] = b1.x; Bs[kb + 5][lr] = b1.y; Bs[kb + 6][lr] = b1.z; Bs[kb + 7][lr] = b1.w;
        Bs[kb + 8][lr] = b2.x; Bs[kb + 9][lr] = b2.y; Bs[kb + 10][lr] = b2.z; Bs[kb + 11][lr] = b2.w;
        Bs[kb + 12][lr] = b3.x; Bs[kb + 13][lr] = b3.y; Bs[kb + 14][lr] = b3.z; Bs[kb + 15][lr] = b3.w;
        __syncthreads();
#pragma unroll 8
        for (int k = 0; k < 32; k++) {
            float4 x0 = *(const float4*)&As[k][r0];
            float4 x1 = *(const float4*)&As[k][64 + r0];
            ulonglong2 B0 = *(const ulonglong2*)&Bs[k][c0];
            ulonglong2 B1 = *(const ulonglong2*)&Bs[k][64 + c0];
            float ar[8] = {x0.x, x0.y, x0.z, x0.w, x1.x, x1.y, x1.z, x1.w};
            unsigned long long bv[4] = {B0.x, B0.y, B1.x, B1.y};
#pragma unroll
            for (int r = 0; r < 8; r++) {
                unsigned long long av;
                asm("mov.b64 %0, {%1, %1};" : "=l"(av) : "r"(__float_as_uint(ar[r])));
#pragma unroll
                for (int c = 0; c < 4; c++)
                    asm("fma.rn.f32x2 %0, %1, %2, %0;"
                        : "+l"(acc2[r][c]) : "l"(av), "l"(bv[c]));
            }
        }
    }

    float dot[8][8];
#pragma unroll
    for (int r = 0; r < 8; r++)
#pragma unroll
        for (int c = 0; c < 4; c++) {
            dot[r][2 * c]     = __uint_as_float((unsigned)(acc2[r][c] & 0xFFFFFFFFull));
            dot[r][2 * c + 1] = __uint_as_float((unsigned)(acc2[r][c] >> 32));
        }

    float actT = g_actT;   // written by K2's last block (previous launch)

    int rows[8], cols[8];
#pragma unroll
    for (int u = 0; u < 4; u++) {
        rows[u] = ri + r0 + u;
        rows[4 + u] = ri + 64 + r0 + u;
        cols[u] = rj + c0 + u;
        cols[4 + u] = rj + 64 + c0 + u;
    }
    float ti[8], tj[8];
    int li[8], lj[8];
#pragma unroll
    for (int u = 0; u < 8; u++) {
        ti[u] = t[rows[u]];
        tj[u] = t[cols[u]];
        li[u] = g_low[rows[u]];
        lj[u] = g_low[cols[u]];
    }
    float pMin[8], nMax[8], cMin[8], cMax[8];
#pragma unroll
    for (int u = 0; u < 8; u++) {
        pMin[u] = 3.402823466e38f; nMax[u] = -3.402823466e38f;
        cMin[u] = 3.402823466e38f; cMax[u] = -3.402823466e38f;
    }
#pragma unroll
    for (int r = 0; r < 8; r++) {
#pragma unroll
        for (int c = 0; c < 8; c++) {
            float ad = fabsf(ti[r] - tj[c]);
            if (ad < actT) {
                float dv = dot[r][c];
                bool neq = rows[r] != cols[c];
                if (lj[c]) { if (neq) pMin[r] = fminf(pMin[r], dv); }
                else nMax[r] = fmaxf(nMax[r], dv);
                if (li[r]) { if (neq) cMin[c] = fminf(cMin[c], dv); }
                else cMax[c] = fmaxf(cMax[c], dv);
            }
        }
    }
#pragma unroll
    for (int s = 8; s > 0; s >>= 1) {
#pragma unroll
        for (int r = 0; r < 8; r++) {
            pMin[r] = fminf(pMin[r], __shfl_down_sync(0xffffffffu, pMin[r], s, 16));
            nMax[r] = fmaxf(nMax[r], __shfl_down_sync(0xffffffffu, nMax[r], s, 16));
        }
    }
    if ((tid & 15) == 0) {
#pragma unroll
        for (int r = 0; r < 8; r++) {
            if (pMin[r] < 3.0e38f) atomicMax(&g_rowMinInv[rows[r]], ~encodeF(pMin[r]));
            if (nMax[r] > -3.0e38f) atomicMax(&g_rowMaxNeg[rows[r]], encodeF(nMax[r]));
        }
    }
    unsigned eMinI[8], eMax[8];
#pragma unroll
    for (int u = 0; u < 8; u++) {
        eMinI[u] = ~encodeF(cMin[u]);
        eMax[u] = encodeF(cMax[u]);
        eMinI[u] = max(eMinI[u], __shfl_xor_sync(0xffffffffu, eMinI[u], 16));
        eMax[u] = max(eMax[u], __shfl_xor_sync(0xffffffffu, eMax[u], 16));
    }
    int wrp = tid >> 5;
    __syncthreads();
    if ((tid & 31) < 16) {
#pragma unroll
        for (int u = 0; u < 4; u++) {
            sColMin[wrp * 128 + c0 + u] = eMinI[u];
            sColMin[wrp * 128 + 64 + c0 + u] = eMinI[4 + u];
            sColMax[wrp * 128 + c0 + u] = eMax[u];
            sColMax[wrp * 128 + 64 + c0 + u] = eMax[4 + u];
        }
    }
    __syncthreads();
    if (tid < 128) {
        unsigned v = sColMin[tid];
#pragma unroll
        for (int w = 1; w < 8; w++) v = max(v, sColMin[w * 128 + tid]);
        if (v > 0x00800000u) atomicMax(&g_rowMinInv[rj + tid], v);
    } else {
        int c = tid - 128;
        unsigned v = sColMax[c];
#pragma unroll
        for (int w = 1; w < 8; w++) v = max(v, sColMax[w * 128 + c]);
        if (v > 0x01000000u) atomicMax(&g_rowMaxNeg[rj + c], v);
    }

    // ---- last gemm block: final loss + reset all accumulators ----
    __threadfence();
    if (tid == 0) sLast = (atomicAdd(&g_doneCtr[2], 1u) == (unsigned)(GB - 1)) ? 1 : 0;
    __syncthreads();
    if (!sLast) return;

    float sum = 0.0f;
    unsigned cnt = 0u;
    for (int i = tid; i < N; i += 256) {
        if (g_low[i] == 0) continue;
        unsigned rInv = __ldcg(&g_rowMinInv[i]);
        if (rInv == 0u) continue;
        unsigned en = __ldcg(&g_rowMaxNeg[i]);
        if (en == 0u) continue;
        float minDot = decodeF(~rInv);
        float maxDot = decodeF(en);
        float hp = sqrtf(fmaxf(2.0f - 2.0f * minDot, 1e-12f));
        float hn = sqrtf(fmaxf(2.0f - 2.0f * maxDot, 1e-12f));
        float tl = hp - hn + 0.5f;
        if (tl < 0.0f) tl = 0.0f;
        sum += tl;
        cnt++;
    }
    int lane = tid & 31;
#pragma unroll
    for (int s = 16; s > 0; s >>= 1) {
        sum += __shfl_down_sync(0xffffffffu, sum, s);
        cnt += __shfl_down_sync(0xffffffffu, cnt, s);
    }
    __syncthreads();
    float* fred = (float*)sbuf;
    unsigned* ured = (unsigned*)(sbuf + 64);
    if (lane == 0) { fred[wrp] = sum; ured[wrp] = cnt; }
    __syncthreads();
    if (wrp == 0) {
        float s2 = (lane < 8) ? fred[lane] : 0.0f;
        unsigned c2 = (lane < 8) ? ured[lane] : 0u;
#pragma unroll
        for (int s = 4; s > 0; s >>= 1) {
            s2 += __shfl_down_sync(0xffffffffu, s2, s);
            c2 += __shfl_down_sync(0xffffffffu, c2, s);
        }
        if (lane == 0) out[0] = s2 / (float)(c2 > 0u ? c2 : 1u);
    }
    for (int i = tid; i < out_size; i += 256)
        if (i > 0) out[i] = 0.0f;

    // resets (identity 0 everywhere); g_hist20 re-zeroed by next K1
    for (int x = tid; x < 4096; x += 256) {
        g_hist1[x] = 0u;
        g_hist2[x] = 0u;
        g_rowMinInv[x] = 0u;
        g_rowMaxNeg[x] = 0u;
    }
    if (tid < 4) g_doneCtr[tid] = 0u;
    if (tid == 0) {
        g_zeroPairs = 0u;
        g_minCrossInv = 0u;
    }
}

// ---------------- launch ----------------
extern "C" void kernel_launch(void* const* d_in, const int* in_sizes, int n_in,
                              void* d_out, int out_size) {
    const float* emb = (const float*)d_in[0];
    const float* tg = (const float*)d_in[1];
    const float* au = (const float*)d_in[2];
    float* out = (float*)d_out;

    prepPass1K<<<HB1 + 128 + 1, 256>>>(tg, emb, au);   // 1
    pass2K<<<HB2, 256>>>(tg);                          // 2
    gemmK<<<GB, 256>>>(tg, out, out_size);             // 3
}

// round 13
// speedup vs baseline: 1.0926x; 1.0926x over previous
#include <cuda_runtime.h>
#include <cuda_bf16.h>
#include <cstdint>

#define N 4096
#define D 128
#define HB1 256   // pass1 blocks
#define HB2 256   // pass2 blocks
#define GB  528   // gemm blocks

// smem tile layout: 128 rows x 256B, padded stride 272B (bank-conflict-free ldmatrix)
#define TSTRIDE 272
#define TILE_B (128 * TSTRIDE)     // 34816
#define T_AHI 0
#define T_ALO TILE_B
#define T_BHI (2 * TILE_B)
#define T_BLO (3 * TILE_B)
#define DYN_SMEM (4 * TILE_B)      // 139264

// ---------------- device globals (all accumulators have identity == 0) ----------------
__device__ __align__(16) __nv_bfloat16 g_ahi[N * D];
__device__ __align__(16) __nv_bfloat16 g_alo[N * D];
__device__ unsigned char g_low[N];
__device__ unsigned g_rowMinInv[N];      // ~encodeF(min pos-dot), atomicMax, 0 = empty
__device__ unsigned g_rowMaxNeg[N];      // encodeF(max neg-dot), atomicMax, 0 = empty
__device__ unsigned g_hist1[4096];
__device__ unsigned g_hist2[4096];
__device__ unsigned g_hist20[1 << 20];   // exact-value hist within p1 prefix (bits 19:0)
__device__ unsigned g_zeroPairs;
__device__ unsigned g_doneCtr[4];
__device__ unsigned g_p1, g_r1, g_mLo, g_mHi;
__device__ float    g_frac;
__device__ unsigned g_minCrossInv;       // ~min b with top12 > p1, atomicMax, 0 = empty
__device__ float    g_actT;

__device__ __forceinline__ unsigned encodeF(float f) {
    unsigned u = __float_as_uint(f);
    return (u & 0x80000000u) ? ~u : (u | 0x80000000u);
}
__device__ __forceinline__ float decodeF(unsigned u) {
    return (u & 0x80000000u) ? __uint_as_float(u & 0x7FFFFFFFu)
                             : __uint_as_float(~u);
}

__device__ __forceinline__ void rankMath(unsigned z, unsigned& mLo, unsigned& mHi, float& frac) {
    unsigned long long n = 16773120ull - 2ull * (unsigned long long)z;
    float nf = (float)(n - 1ull);
    float pos = 0.2f * nf;
    float lof = floorf(pos);
    frac = pos - lof;
    unsigned fl = (unsigned)lof;
    mLo = fl >> 1;
    mHi = (fl + 1u) >> 1;
}

__device__ __forceinline__ uint32_t smem_u32(const void* p) {
    uint32_t a;
    asm("{ .reg .u64 tmp; cvta.to.shared.u64 tmp, %1; cvt.u32.u64 %0, tmp; }" : "=r"(a) : "l"(p));
    return a;
}
__device__ __forceinline__ void ldsm4(unsigned* r, unsigned addr) {
    asm volatile("ldmatrix.sync.aligned.m8n8.x4.shared.b16 {%0,%1,%2,%3}, [%4];"
                 : "=r"(r[0]), "=r"(r[1]), "=r"(r[2]), "=r"(r[3]) : "r"(addr));
}
__device__ __forceinline__ void mma16816(float* d, const unsigned* a, unsigned b0, unsigned b1) {
    asm volatile("mma.sync.aligned.m16n8k16.row.col.f32.bf16.bf16.f32 "
                 "{%0,%1,%2,%3}, {%4,%5,%6,%7}, {%8,%9}, {%0,%1,%2,%3};"
                 : "+f"(d[0]), "+f"(d[1]), "+f"(d[2]), "+f"(d[3])
                 : "r"(a[0]), "r"(a[1]), "r"(a[2]), "r"(a[3]), "r"(b0), "r"(b1));
}

// ---- histogram locate helpers (verified R8-R12) ----
__device__ void locateG4096(const unsigned* gh, unsigned rank,
                            volatile unsigned* wS,
                            volatile unsigned* outBin, volatile unsigned* outRem) {
    int tid = threadIdx.x, lane = tid & 31, wid = tid >> 5;
    unsigned hl[16];
    unsigned lsum = 0;
#pragma unroll
    for (int k = 0; k < 16; k++) { hl[k] = __ldcg(&gh[tid * 16 + k]); lsum += hl[k]; }
    unsigned v = lsum;
#pragma unroll
    for (int s = 1; s < 32; s <<= 1) {
        unsigned o = __shfl_up_sync(0xffffffffu, v, s);
        if (lane >= s) v += o;
    }
    if (lane == 31) wS[wid] = v;
    __syncthreads();
    if (tid == 0) { unsigned run = 0; for (int w = 0; w < 8; w++) { run += wS[w]; wS[w] = run; } }
    __syncthreads();
    unsigned cum = (v - lsum) + (wid ? wS[wid - 1] : 0u);
#pragma unroll
    for (int k = 0; k < 16; k++) {
        unsigned h = hl[k];
        if (h && rank >= cum && rank < cum + h) { *outBin = (unsigned)(tid * 16 + k); *outRem = rank - cum; }
        cum += h;
    }
    __syncthreads();
}

__device__ void locateG256(const unsigned* gh, unsigned rank,
                           volatile unsigned* wS,
                           volatile unsigned* outBin, volatile unsigned* outRem,
                           volatile unsigned* outCnt) {
    int tid = threadIdx.x, lane = tid & 31, wid = tid >> 5;
    unsigned h = __ldcg(&gh[tid]);
    unsigned v = h;
#pragma unroll
    for (int s = 1; s < 32; s <<= 1) {
        unsigned o = __shfl_up_sync(0xffffffffu, v, s);
        if (lane >= s) v += o;
    }
    if (lane == 31) wS[wid] = v;
    __syncthreads();
    if (tid == 0) { unsigned run = 0; for (int w = 0; w < 8; w++) { run += wS[w]; wS[w] = run; } }
    __syncthreads();
    unsigned cum = (v - h) + (wid ? wS[wid - 1] : 0u);
    if (h && rank >= cum && rank < cum + h) { *outBin = (unsigned)tid; *outRem = rank - cum; *outCnt = h; }
    __syncthreads();
}

__device__ void locateS4096(const unsigned* h, unsigned rank,
                            volatile unsigned* wS,
                            volatile unsigned* outBin, volatile unsigned* outRem) {
    int tid = threadIdx.x, lane = tid & 31, wid = tid >> 5;
    unsigned hl[16];
    unsigned lsum = 0;
#pragma unroll
    for (int k = 0; k < 16; k++) { hl[k] = h[tid * 16 + k]; lsum += hl[k]; }
    unsigned v = lsum;
#pragma unroll
    for (int s = 1; s < 32; s <<= 1) {
        unsigned o = __shfl_up_sync(0xffffffffu, v, s);
        if (lane >= s) v += o;
    }
    if (lane == 31) wS[wid] = v;
    __syncthreads();
    if (tid == 0) { unsigned run = 0; for (int w = 0; w < 8; w++) { run += wS[w]; wS[w] = run; } }
    __syncthreads();
    unsigned cum = (v - lsum) + (wid ? wS[wid - 1] : 0u);
#pragma unroll
    for (int k = 0; k < 16; k++) {
        unsigned hh = hl[k];
        if (hh && rank >= cum && rank < cum + hh) { *outBin = (unsigned)(tid * 16 + k); *outRem = rank - cum; }
        cum += hh;
    }
    __syncthreads();
}

// ================ K1: [pass1: 0-255] + [normalize(bf16 split)+zero20: 256-383] + [median: 384] ================
__global__ __launch_bounds__(256) void prepPass1K(const float* __restrict__ t,
                                                  const float* __restrict__ emb,
                                                  const float* __restrict__ au) {
    __shared__ __align__(16) unsigned char sbuf[32768];
    __shared__ unsigned wS[8];
    __shared__ unsigned sA, sB_;
    __shared__ unsigned sAgg;
    __shared__ int sLast;
    int tid = threadIdx.x;
    int bid = blockIdx.x;

    if (bid < HB1) {
        float4* tsv4 = (float4*)sbuf;
        unsigned* hist = (unsigned*)(sbuf + 16384);
        const float* tss = (const float*)tsv4;
        for (int k = tid; k < 1024; k += 256) tsv4[k] = ((const float4*)t)[k];
        for (int x = tid; x < 4096; x += 256) hist[x] = 0u;
        if (tid == 0) sAgg = 0u;
        __syncthreads();

        unsigned zc = 0u;
        for (int i = bid; i < N; i += HB1) {
            float ti = tss[i];
            int v0 = (i + 1) >> 2;
            for (int v = v0 + tid; v < 1024; v += 256) {
                float4 w = tsv4[v];
                int jb = v << 2;
#pragma unroll
                for (int k = 0; k < 4; k++) {
                    float tj = (k == 0) ? w.x : (k == 1) ? w.y : (k == 2) ? w.z : w.w;
                    if (jb + k > i) {
                        unsigned b = __float_as_uint(fabsf(ti - tj));
                        if (b == 0u) zc++;
                        else atomicAdd(&hist[b >> 20], 1u);
                    }
                }
            }
        }
        __syncthreads();
        for (int x = tid; x < 4096; x += 256)
            if (hist[x]) atomicAdd(&g_hist1[x], hist[x]);
#pragma unroll
        for (int s = 16; s > 0; s >>= 1) zc += __shfl_xor_sync(0xffffffffu, zc, s);
        if ((tid & 31) == 0 && zc) atomicAdd(&sAgg, zc);
        __syncthreads();
        if (tid == 0 && sAgg) atomicAdd(&g_zeroPairs, sAgg);

        __threadfence();
        if (tid == 0) sLast = (atomicAdd(&g_doneCtr[0], 1u) == (unsigned)(HB1 - 1)) ? 1 : 0;
        __syncthreads();
        if (!sLast) return;

        unsigned z = __ldcg(&g_zeroPairs);
        unsigned mLo, mHi; float frac;
        rankMath(z, mLo, mHi, frac);
        locateG4096(g_hist1, mLo, wS, &sA, &sB_);
        if (tid == 0) {
            g_p1 = sA; g_r1 = sB_;
            g_mLo = mLo; g_mHi = mHi; g_frac = frac;
        }
        return;
    }

    if (bid < HB1 + 128) {
        // normalize 32 rows -> bf16 hi/lo split + zero hist20 slice
        int nb = bid - HB1;
        for (int x = tid; x < 8192; x += 256) g_hist20[nb * 8192 + x] = 0u;
        int warp = tid >> 5, lane = tid & 31;
#pragma unroll
        for (int q = 0; q < 4; q++) {
            int row = nb * 32 + warp * 4 + q;
            const float4* p = (const float4*)(emb + (size_t)row * D);
            float4 v = p[lane];
            float ss = v.x * v.x + v.y * v.y + v.z * v.z + v.w * v.w;
#pragma unroll
            for (int st = 16; st > 0; st >>= 1) ss += __shfl_xor_sync(0xffffffffu, ss, st);
            float inv = 1.0f / fmaxf(sqrtf(ss), 1e-12f);
            float o[4] = {v.x * inv, v.y * inv, v.z * inv, v.w * inv};
            __nv_bfloat16 h[4], l[4];
#pragma unroll
            for (int u = 0; u < 4; u++) {
                h[u] = __float2bfloat16(o[u]);
                l[u] = __float2bfloat16(o[u] - __bfloat162float(h[u]));
            }
            __nv_bfloat162* ph = (__nv_bfloat162*)(g_ahi + (size_t)row * D);
            __nv_bfloat162* pl = (__nv_bfloat162*)(g_alo + (size_t)row * D);
            ph[lane * 2]     = __nv_bfloat162{h[0], h[1]};
            ph[lane * 2 + 1] = __nv_bfloat162{h[2], h[3]};
            pl[lane * 2]     = __nv_bfloat162{l[0], l[1]};
            pl[lane * 2 + 1] = __nv_bfloat162{l[2], l[3]};
        }
        return;
    }

    // median of au via 3-level radix select (ranks 2047, 2048)
    {
        unsigned* e = (unsigned*)sbuf;
        unsigned* h = (unsigned*)(sbuf + 16384);
        for (int i = tid; i < N; i += 256) e[i] = encodeF(au[i]);
        __syncthreads();
        float vals[2];
#pragma unroll 1
        for (int r = 0; r < 2; r++) {
            unsigned rank = 2047u + (unsigned)r;
            for (int x = tid; x < 4096; x += 256) h[x] = 0u;
            __syncthreads();
            for (int i = tid; i < N; i += 256) atomicAdd(&h[e[i] >> 20], 1u);
            __syncthreads();
            locateS4096(h, rank, wS, &sA, &sB_);
            unsigned b1 = sA, r1 = sB_;
            __syncthreads();
            for (int x = tid; x < 4096; x += 256) h[x] = 0u;
            __syncthreads();
            for (int i = tid; i < N; i += 256)
                if ((e[i] >> 20) == b1) atomicAdd(&h[(e[i] >> 8) & 0xFFFu], 1u);
            __syncthreads();
            locateS4096(h, r1, wS, &sA, &sB_);
            unsigned b2 = sA, r2 = sB_;
            unsigned pfx = (b1 << 12) | b2;
            __syncthreads();
            for (int x = tid; x < 4096; x += 256) h[x] = 0u;
            __syncthreads();
            for (int i = tid; i < N; i += 256)
                if ((e[i] >> 8) == pfx) atomicAdd(&h[e[i] & 0xFFu], 1u);
            __syncthreads();
            locateS4096(h, r2, wS, &sA, &sB_);
            unsigned b3 = sA;
            __syncthreads();
            vals[r] = decodeF((b1 << 20) | (b2 << 8) | b3);
        }
        float th = __fadd_rn(__fmul_rn(vals[0], 0.5f), __fmul_rn(vals[1], 0.5f));
        for (int i = tid; i < N; i += 256) g_low[i] = (au[i] < th) ? 1 : 0;
    }
}

// ================ K2: pass 2 (hist2 + exact hist20 + cross-min; last block selects actT) ================
__global__ __launch_bounds__(256) void pass2K(const float* __restrict__ t) {
    __shared__ __align__(16) unsigned char sbuf[32768];
    __shared__ unsigned wS[8];
    __shared__ unsigned sA, sB_, sC_, sD_;
    __shared__ unsigned sAgg;
    __shared__ int sLast;
    int tid = threadIdx.x;

    float4* tsv4 = (float4*)sbuf;
    unsigned* sh2 = (unsigned*)(sbuf + 16384);
    const float* tss = (const float*)tsv4;
    for (int k = tid; k < 1024; k += 256) tsv4[k] = ((const float4*)t)[k];
    for (int x = tid; x < 4096; x += 256) sh2[x] = 0u;
    if (tid == 0) sAgg = 0u;
    unsigned p1 = g_p1;
    __syncthreads();

    unsigned myInv = 0u;
    for (int i = blockIdx.x; i < N; i += HB2) {
        float ti = tss[i];
        int v0 = (i + 1) >> 2;
        for (int v = v0 + tid; v < 1024; v += 256) {
            float4 w = tsv4[v];
            int jb = v << 2;
#pragma unroll
            for (int k = 0; k < 4; k++) {
                float tj = (k == 0) ? w.x : (k == 1) ? w.y : (k == 2) ? w.z : w.w;
                if (jb + k > i) {
                    unsigned b = __float_as_uint(fabsf(ti - tj));
                    if (b != 0u) {
                        unsigned t12 = b >> 20;
                        if (t12 == p1) {
                            atomicAdd(&sh2[(b >> 8) & 0xFFFu], 1u);
                            atomicAdd(&g_hist20[b & 0xFFFFFu], 1u);
                        } else if (t12 > p1) {
                            myInv = max(myInv, ~b);
                        }
                    }
                }
            }
        }
    }
    __syncthreads();
    for (int x = tid; x < 4096; x += 256)
        if (sh2[x]) atomicAdd(&g_hist2[x], sh2[x]);
#pragma unroll
    for (int s = 16; s > 0; s >>= 1) myInv = max(myInv, __shfl_xor_sync(0xffffffffu, myInv, s));
    if ((tid & 31) == 0 && myInv) atomicMax(&sAgg, myInv);
    __syncthreads();
    if (tid == 0 && sAgg) atomicMax(&g_minCrossInv, sAgg);

    __threadfence();
    if (tid == 0) sLast = (atomicAdd(&g_doneCtr[1], 1u) == (unsigned)(HB2 - 1)) ? 1 : 0;
    __syncthreads();
    if (!sLast) return;

    unsigned r1 = g_r1;
    locateG4096(g_hist2, r1, wS, &sA, &sB_);
    unsigned bin2 = sA, rem2 = sB_;
    __syncthreads();
    locateG256(&g_hist20[bin2 << 8], rem2, wS, &sA, &sB_, &sC_);
    unsigned bin3 = sA, rem3 = sB_, cnt3 = sC_;
    __syncthreads();
    if (tid == 0) { sA = 0xFFFFFFFFu; sB_ = 0xFFFFFFFFu; sD_ = 0xFFFFFFFFu; }
    __syncthreads();
    if ((unsigned)tid > bin3 && __ldcg(&g_hist20[(bin2 << 8) + tid]) != 0u)
        atomicMin(&sA, (unsigned)tid);
#pragma unroll
    for (int k = 0; k < 16; k++) {
        unsigned idx = (unsigned)tid * 16u + (unsigned)k;
        if (idx > bin2 && __ldcg(&g_hist2[idx]) != 0u) atomicMin(&sB_, idx);
    }
    __syncthreads();
    unsigned nextA = sA, nbin2 = sB_;
    if (nbin2 != 0xFFFFFFFFu) {
        if (__ldcg(&g_hist20[(nbin2 << 8) + tid]) != 0u) atomicMin(&sD_, (unsigned)tid);
    }
    __syncthreads();
    if (tid == 0) {
        unsigned vlo = (p1 << 20) | (bin2 << 8) | bin3;
        unsigned mLo = g_mLo, mHi = g_mHi;
        float frac = g_frac;
        unsigned mAb = 0xFFFFFFFFu;
        if (nextA != 0xFFFFFFFFu) mAb = min(mAb, (p1 << 20) | (bin2 << 8) | nextA);
        if (nbin2 != 0xFFFFFFFFu && sD_ != 0xFFFFFFFFu)
            mAb = min(mAb, (p1 << 20) | (nbin2 << 8) | sD_);
        unsigned crossInv = __ldcg(&g_minCrossInv);
        if (crossInv) mAb = min(mAb, ~crossInv);
        bool same = (mHi == mLo) || (rem3 + 1u < cnt3);
        float flo = __uint_as_float(vlo);
        float fhi = same ? flo : __uint_as_float(mAb);
        g_actT = __fadd_rn(__fmul_rn(flo, 1.0f - frac), __fmul_rn(fhi, frac));
    }
}

// ================ K3: HMMA bf16-split GEMM + masked epilogue; last block: final + resets ================
extern __shared__ unsigned char g_dyn[];
__global__ __launch_bounds__(256) void gemmHK(const float* __restrict__ t,
                                              float* __restrict__ out, int out_size) {
    __shared__ float tCol[128];
    __shared__ unsigned char lowCol[128];
    __shared__ unsigned sColMinI[4][128];
    __shared__ unsigned sColMax[4][128];
    __shared__ float fred[8];
    __shared__ unsigned ured[8];
    __shared__ int sLast;

    int tid = threadIdx.x;     // 256
    int warp = tid >> 5, lane = tid & 31;

    // triangular tile mapping
    int b = blockIdx.x;
    int bi = 0;
    while (b >= 32 - bi) { b -= 32 - bi; bi++; }
    int bj = bi + b;
    int ri = bi * 128, rj = bj * 128;

    uint32_t sbase = smem_u32(g_dyn);

    // ---- load 4 tiles (row-major, TSTRIDE pad) ----
    for (int i = tid; i < 2048; i += 256) {
        int row = i >> 4, ch = i & 15;
        unsigned off = (unsigned)row * TSTRIDE + (unsigned)ch * 16u;
        *(uint4*)(g_dyn + T_AHI + off) = ((const uint4*)(g_ahi + (size_t)(ri + row) * D))[ch];
        *(uint4*)(g_dyn + T_ALO + off) = ((const uint4*)(g_alo + (size_t)(ri + row) * D))[ch];
        *(uint4*)(g_dyn + T_BHI + off) = ((const uint4*)(g_ahi + (size_t)(rj + row) * D))[ch];
        *(uint4*)(g_dyn + T_BLO + off) = ((const uint4*)(g_alo + (size_t)(rj + row) * D))[ch];
    }
    if (tid < 128) {
        tCol[tid] = t[rj + tid];
        lowCol[tid] = g_low[rj + tid];
    }
    __syncthreads();

    int wr = warp >> 1, wc = warp & 1;
    int R = wr * 32, C = wc * 64;

    float acc[2][8][4];
#pragma unroll
    for (int mt = 0; mt < 2; mt++)
#pragma unroll
        for (int nt = 0; nt < 8; nt++)
#pragma unroll
            for (int q = 0; q < 4; q++) acc[mt][nt][q] = 0.0f;

    // A fragment address pieces (lane-dependent)
    unsigned aRow = (unsigned)((lane & 7) + ((lane >> 3) & 1) * 8);
    unsigned aByte = (unsigned)((lane >> 4) * 16);
    unsigned bRow = (unsigned)(((lane >> 4) * 8) + (lane & 7));
    unsigned bByte = (unsigned)(((lane >> 3) & 1) * 16);

#pragma unroll 1
    for (int split = 0; split < 3; split++) {
        unsigned At = sbase + ((split == 2) ? T_ALO : T_AHI);
        unsigned Bt = sbase + ((split == 1) ? T_BLO : T_BHI);
#pragma unroll
        for (int kb = 0; kb < 8; kb++) {
            unsigned kByte = (unsigned)kb * 32u;
            unsigned a[2][4];
#pragma unroll
            for (int mt = 0; mt < 2; mt++) {
                unsigned addr = At + (unsigned)(R + mt * 16 + aRow) * TSTRIDE + kByte + aByte;
                ldsm4(a[mt], addr);
            }
#pragma unroll
            for (int ntp = 0; ntp < 4; ntp++) {
                unsigned bm[4];
                unsigned addr = Bt + (unsigned)(C + ntp * 16 + bRow) * TSTRIDE + kByte + bByte;
                ldsm4(bm, addr);
                mma16816(acc[0][ntp * 2],     a[0], bm[0], bm[1]);
                mma16816(acc[0][ntp * 2 + 1], a[0], bm[2], bm[3]);
                mma16816(acc[1][ntp * 2],     a[1], bm[0], bm[1]);
                mma16816(acc[1][ntp * 2 + 1], a[1], bm[2], bm[3]);
            }
        }
    }

    // ---- masked epilogue ----
    float actT = g_actT;
    float pMin[4], nMax[4];
#pragma unroll
    for (int u = 0; u < 4; u++) { pMin[u] = 3.402823466e38f; nMax[u] = -3.402823466e38f; }
    unsigned cMinI[8][2], cMax[8][2];
#pragma unroll
    for (int nt = 0; nt < 8; nt++) { cMinI[nt][0] = cMinI[nt][1] = 0u; cMax[nt][0] = cMax[nt][1] = 0u; }

#pragma unroll
    for (int mt = 0; mt < 2; mt++) {
        int rA = ri + R + mt * 16 + (lane >> 2);
        int rB = rA + 8;
        float tA = t[rA], tB = t[rB];
        int lA = g_low[rA], lB = g_low[rB];
#pragma unroll
        for (int nt = 0; nt < 8; nt++) {
            int lc0 = C + nt * 8 + (lane & 3) * 2;
#pragma unroll
            for (int s = 0; s < 2; s++) {
                int lc = lc0 + s;
                int gcol = rj + lc;
                float tc = tCol[lc];
                int lj = lowCol[lc];
                // element (rA, gcol) = acc[mt][nt][s]
                {
                    float dv = acc[mt][nt][s];
                    float ad = fabsf(tA - tc);
                    if (ad < actT) {
                        bool neq = rA != gcol;
                        if (lj) { if (neq) pMin[mt * 2] = fminf(pMin[mt * 2], dv); }
                        else nMax[mt * 2] = fmaxf(nMax[mt * 2], dv);
                        if (lA && neq) cMinI[nt][s] = max(cMinI[nt][s], ~encodeF(dv));
                        if (!lA) cMax[nt][s] = max(cMax[nt][s], encodeF(dv));
                    }
                }
                // element (rB, gcol) = acc[mt][nt][2+s]
                {
                    float dv = acc[mt][nt][2 + s];
                    float ad = fabsf(tB - tc);
                    if (ad < actT) {
                        bool neq = rB != gcol;
                        if (lj) { if (neq) pMin[mt * 2 + 1] = fminf(pMin[mt * 2 + 1], dv); }
                        else nMax[mt * 2 + 1] = fmaxf(nMax[mt * 2 + 1], dv);
                        if (lB && neq) cMinI[nt][s] = max(cMinI[nt][s], ~encodeF(dv));
                        if (!lB) cMax[nt][s] = max(cMax[nt][s], encodeF(dv));
                    }
                }
            }
        }
    }
    // row-side: reduce across the 4 lanes of each quad (same rows)
#pragma unroll
    for (int s = 1; s < 4; s <<= 1) {
#pragma unroll
        for (int u = 0; u < 4; u++) {
            pMin[u] = fminf(pMin[u], __shfl_xor_sync(0xffffffffu, pMin[u], s));
            nMax[u] = fmaxf(nMax[u], __shfl_xor_sync(0xffffffffu, nMax[u], s));
        }
    }
    if ((lane & 3) == 0) {
#pragma unroll
        for (int mt = 0; mt < 2; mt++) {
            int rA = ri + R + mt * 16 + (lane >> 2);
            int rB = rA + 8;
            if (pMin[mt * 2] < 3.0e38f) atomicMax(&g_rowMinInv[rA], ~encodeF(pMin[mt * 2]));
            if (nMax[mt * 2] > -3.0e38f) atomicMax(&g_rowMaxNeg[rA], encodeF(nMax[mt * 2]));
            if (pMin[mt * 2 + 1] < 3.0e38f) atomicMax(&g_rowMinInv[rB], ~encodeF(pMin[mt * 2 + 1]));
            if (nMax[mt * 2 + 1] > -3.0e38f) atomicMax(&g_rowMaxNeg[rB], encodeF(nMax[mt * 2 + 1]));
        }
    }
    // col-side: reduce across groups (lanes differing in bits 2-4 share cols)
#pragma unroll
    for (int s = 4; s < 32; s <<= 1) {
#pragma unroll
        for (int nt = 0; nt < 8; nt++)
#pragma unroll
            for (int q = 0; q < 2; q++) {
                cMinI[nt][q] = max(cMinI[nt][q], __shfl_xor_sync(0xffffffffu, cMinI[nt][q], s));
                cMax[nt][q] = max(cMax[nt][q], __shfl_xor_sync(0xffffffffu, cMax[nt][q], s));
            }
    }
    if (lane < 4) {
#pragma unroll
        for (int nt = 0; nt < 8; nt++)
#pragma unroll
            for (int q = 0; q < 2; q++) {
                int lc = C + nt * 8 + lane * 2 + q;
                sColMinI[wr][lc] = cMinI[nt][q];
                sColMax[wr][lc] = cMax[nt][q];
            }
    }
    __syncthreads();
    if (tid < 128) {
        unsigned vI = sColMinI[0][tid], vX = sColMax[0][tid];
#pragma unroll
        for (int w = 1; w < 4; w++) {
            vI = max(vI, sColMinI[w][tid]);
            vX = max(vX, sColMax[w][tid]);
        }
        if (vI) atomicMax(&g_rowMinInv[rj + tid], vI);
        if (vX) atomicMax(&g_rowMaxNeg[rj + tid], vX);
    }

    // ---- last block: final loss + resets ----
    __threadfence();
    if (tid == 0) sLast = (atomicAdd(&g_doneCtr[2], 1u) == (unsigned)(GB - 1)) ? 1 : 0;
    __syncthreads();
    if (!sLast) return;

    float sum = 0.0f;
    unsigned cnt = 0u;
    for (int i = tid; i < N; i += 256) {
        if (g_low[i] == 0) continue;
        unsigned rInv = __ldcg(&g_rowMinInv[i]);
        if (rInv == 0u) continue;
        unsigned en = __ldcg(&g_rowMaxNeg[i]);
        if (en == 0u) continue;
        float minDot = decodeF(~rInv);
        float maxDot = decodeF(en);
        float hp = sqrtf(fmaxf(2.0f - 2.0f * minDot, 1e-12f));
        float hn = sqrtf(fmaxf(2.0f - 2.0f * maxDot, 1e-12f));
        float tl = hp - hn + 0.5f;
        if (tl < 0.0f) tl = 0.0f;
        sum += tl;
        cnt++;
    }
#pragma unroll
    for (int s = 16; s > 0; s >>= 1) {
        sum += __shfl_down_sync(0xffffffffu, sum, s);
        cnt += __shfl_down_sync(0xffffffffu, cnt, s);
    }
    if (lane == 0) { fred[warp] = sum; ured[warp] = cnt; }
    __syncthreads();
    if (tid == 0) {
        float s2 = 0.0f;
        unsigned c2 = 0u;
#pragma unroll
        for (int w = 0; w < 8; w++) { s2 += fred[w]; c2 += ured[w]; }
        out[0] = s2 / (float)(c2 > 0u ? c2 : 1u);
    }
    for (int i = tid; i < out_size; i += 256)
        if (i > 0) out[i] = 0.0f;

    for (int x = tid; x < 4096; x += 256) {
        g_hist1[x] = 0u;
        g_hist2[x] = 0u;
        g_rowMinInv[x] = 0u;
        g_rowMaxNeg[x] = 0u;
    }
    if (tid < 4) g_doneCtr[tid] = 0u;
    if (tid == 0) {
        g_zeroPairs = 0u;
        g_minCrossInv = 0u;
    }
}

// ---------------- launch ----------------
extern "C" void kernel_launch(void* const* d_in, const int* in_sizes, int n_in,
                              void* d_out, int out_size) {
    const float* emb = (const float*)d_in[0];
    const float* tg = (const float*)d_in[1];
    const float* au = (const float*)d_in[2];
    float* out = (float*)d_out;

    cudaFuncSetAttribute(gemmHK, cudaFuncAttributeMaxDynamicSharedMemorySize, DYN_SMEM);

    prepPass1K<<<HB1 + 128 + 1, 256>>>(tg, emb, au);     // 1
    pass2K<<<HB2, 256>>>(tg);                            // 2
    gemmHK<<<GB, 256, DYN_SMEM>>>(tg, out, out_size);    // 3
}